// round 10
// baseline (speedup 1.0000x reference)
#include <cuda_runtime.h>
#include <math.h>
#include <cstdint>

#define SQ   2048
#define HID  2048
#define NHEAD 16
#define HD   128
#define QKV_N (3*HID)   // 6144
#define ROWSTRIDE 6144

// Scratch (device globals — no allocation allowed)
__device__ float g_mixed[(size_t)SQ * QKV_N];
__device__ float g_ctx[(size_t)SQ * HID];       // tf32-rounded
__device__ float g_hid_t[(size_t)SQ * HID];     // tf32-rounded hidden
__device__ float g_wqkv_t[(size_t)QKV_N * HID]; // tf32-rounded w_qkv
__device__ float g_wdense_t[(size_t)HID * HID]; // tf32-rounded w_dense

// ---------------------------------------------------------------------------
// Helpers
// ---------------------------------------------------------------------------
__device__ __forceinline__ uint32_t smem_u32(const void* p) {
    uint32_t a;
    asm("{ .reg .u64 t; cvta.to.shared.u64 t, %1; cvt.u32.u64 %0, t; }"
        : "=r"(a) : "l"(p));
    return a;
}
__device__ __forceinline__ void cp_async16(uint32_t d, const void* s) {
    asm volatile("cp.async.cg.shared.global [%0], [%1], 16;"
                 :: "r"(d), "l"(s) : "memory");
}
__device__ __forceinline__ float tf32_rna(float x) {
    uint32_t t;
    asm("cvt.rna.tf32.f32 %0, %1;" : "=r"(t) : "f"(x));
    return __uint_as_float(t);
}
// m16n8k8 tf32 MMA: D += A(16x8,row) * B(8x8,col)
__device__ __forceinline__ void mma_tf32_16n8k8(float* c, const uint32_t* a,
                                                const uint32_t* b) {
    asm volatile(
        "mma.sync.aligned.m16n8k8.row.col.f32.tf32.tf32.f32 "
        "{%0,%1,%2,%3}, {%4,%5,%6,%7}, {%8,%9}, {%0,%1,%2,%3};"
        : "+f"(c[0]), "+f"(c[1]), "+f"(c[2]), "+f"(c[3])
        : "r"(a[0]), "r"(a[1]), "r"(a[2]), "r"(a[3]), "r"(b[0]), "r"(b[1]));
}

// ---------------------------------------------------------------------------
// tf32 rounding kernel (fp32 -> tf32-rounded fp32)
// ---------------------------------------------------------------------------
__global__ void __launch_bounds__(256) cvt_tf32_kernel(
    const float* __restrict__ in, float* __restrict__ out, int n4)
{
    int i = blockIdx.x * blockDim.x + threadIdx.x;
    if (i >= n4) return;
    float4 v = ((const float4*)in)[i];
    v.x = tf32_rna(v.x); v.y = tf32_rna(v.y);
    v.z = tf32_rna(v.z); v.w = tf32_rna(v.w);
    ((float4*)out)[i] = v;
}

// ---------------------------------------------------------------------------
// mma.sync tf32 NT GEMM: C[M,N] = A[M,K]*B[N,K]^T (+bias)
// 128x128 CTA tile, BK=32, 3-stage cp.async pipeline, 128 threads = 4 warps,
// 2x2 warp grid, 64x64 per warp: 32 LDS feed 32 MMAs per k8 (1.0 LDS/MMA).
// ---------------------------------------------------------------------------
#define BK 32
#define PADK 36
#define STAGE_F (2 * 128 * PADK)
#define GSTAGES 3
#define SMEM_GEMM (GSTAGES * STAGE_F * 4)

__global__ void __launch_bounds__(128)
gemm_mma_kernel(const float* __restrict__ A, const float* __restrict__ Bw,
                const float* __restrict__ bias, float* __restrict__ C,
                int N, int K)
{
    extern __shared__ float sm[];
    int tid = threadIdx.x;
    int lane = tid & 31, wid = tid >> 5;
    int g = lane >> 2, tg = lane & 3;
    int wm = wid & 1, wn = wid >> 1;        // 2x2 warps, 64x64 each
    int m0 = blockIdx.y * 128, n0 = blockIdx.x * 128;

    float acc[4][8][4];
#pragma unroll
    for (int im = 0; im < 4; im++)
#pragma unroll
        for (int jn = 0; jn < 8; jn++)
#pragma unroll
            for (int q = 0; q < 4; q++) acc[im][jn][q] = 0.f;

    const int nk = K / BK;
    // fill: thread t owns row t of A-tile and row t of B-tile (8 cp16 each)
    const float* gArow = A  + (size_t)(m0 + tid) * K;
    const float* gBrow = Bw + (size_t)(n0 + tid) * K;

    auto fill = [&](int j) {
        int slot = j % GSTAGES;
        float* dA = sm + slot * STAGE_F + tid * PADK;
        float* dB = dA + 128 * PADK;
        const float* sA = gArow + j * BK;
        const float* sB = gBrow + j * BK;
#pragma unroll
        for (int q = 0; q < 8; q++) {
            cp_async16(smem_u32(dA + q * 4), sA + q * 4);
            cp_async16(smem_u32(dB + q * 4), sB + q * 4);
        }
        asm volatile("cp.async.commit_group;" ::: "memory");
    };

    fill(0);
    fill(1);

    for (int i = 0; i < nk; i++) {
        asm volatile("cp.async.wait_group 1;" ::: "memory");
        __syncthreads();
        if (i + 2 < nk) fill(i + 2);

        int slot = i % GSTAGES;
        const float* As = sm + slot * STAGE_F + (wm * 64) * PADK;
        const float* Bs = sm + slot * STAGE_F + 128 * PADK + (wn * 64) * PADK;

#pragma unroll
        for (int ks = 0; ks < 4; ks++) {
            int k8 = ks * 8;
            uint32_t a[4][4], b[8][2];
#pragma unroll
            for (int im = 0; im < 4; im++) {
                const float* p = As + (im * 16 + g) * PADK + k8 + tg;
                a[im][0] = __float_as_uint(p[0]);
                a[im][1] = __float_as_uint(p[8 * PADK]);
                a[im][2] = __float_as_uint(p[4]);
                a[im][3] = __float_as_uint(p[8 * PADK + 4]);
            }
#pragma unroll
            for (int jn = 0; jn < 8; jn++) {
                const float* p = Bs + (jn * 8 + g) * PADK + k8 + tg;
                b[jn][0] = __float_as_uint(p[0]);
                b[jn][1] = __float_as_uint(p[4]);
            }
#pragma unroll
            for (int im = 0; im < 4; im++)
#pragma unroll
                for (int jn = 0; jn < 8; jn++)
                    mma_tf32_16n8k8(acc[im][jn], a[im], b[jn]);
        }
    }

    // Epilogue: warp covers rows wm*64.., cols wn*64..
#pragma unroll
    for (int im = 0; im < 4; im++) {
#pragma unroll
        for (int jn = 0; jn < 8; jn++) {
            int mrow = m0 + wm * 64 + im * 16 + g;
            int ncol = n0 + wn * 64 + jn * 8 + 2 * tg;
            float b0 = 0.f, b1 = 0.f;
            if (bias) { b0 = bias[ncol]; b1 = bias[ncol + 1]; }
            float2 v0 = make_float2(acc[im][jn][0] + b0, acc[im][jn][1] + b1);
            float2 v1 = make_float2(acc[im][jn][2] + b0, acc[im][jn][3] + b1);
            *(float2*)(C + (size_t)mrow * N + ncol) = v0;
            *(float2*)(C + (size_t)(mrow + 8) * N + ncol) = v1;
        }
    }
}

// ---------------------------------------------------------------------------
// Rotary (in place on g_mixed q,k) + tf32-round q,k,v for the attention MMAs
// ---------------------------------------------------------------------------
__global__ void __launch_bounds__(256) rotary_kernel()
{
    int idx = blockIdx.x * blockDim.x + threadIdx.x;
    if (idx >= SQ * NHEAD * 64) return;
    int j = idx & 63;
    int n = (idx >> 6) & (NHEAD - 1);
    int s = idx >> 10;

    float invf = powf(10000.0f, -(float)(2 * j) / 128.0f);
    float th = (float)s * invf;
    float c = cosf(th), sn = sinf(th);

    float* row = g_mixed + (size_t)s * ROWSTRIDE + n * 384;
    float q1 = row[j], q2 = row[j + 64];
    row[j]      = tf32_rna(q1 * c - q2 * sn);
    row[j + 64] = tf32_rna(q2 * c + q1 * sn);
    float k1 = row[128 + j], k2 = row[128 + j + 64];
    row[128 + j]      = tf32_rna(k1 * c - k2 * sn);
    row[128 + j + 64] = tf32_rna(k2 * c + k1 * sn);
    // round V (2 elements per thread to cover 128)
    row[256 + j]      = tf32_rna(row[256 + j]);
    row[256 + j + 64] = tf32_rna(row[256 + j + 64]);
}

// ---------------------------------------------------------------------------
// Flash attention (causal) on mma.sync tf32 (unchanged from R8 WIN).
// 128 threads = 4 warps, each warp owns 16 query rows. Br=Bc=64, D=128.
// ---------------------------------------------------------------------------
#define ALD 132   // K/Q smem row stride (floats)
#define VLD 68    // V^T smem row stride
#define PLD 76    // P smem row stride
#define ATT_SMEM ((64*ALD + 128*VLD + 64*PLD) * 4)

__global__ void __launch_bounds__(128) attn_mma_kernel()
{
    extern __shared__ float smf[];
    float* Ks = smf;                    // 64 x ALD (also Q staging)
    float* Vt = smf + 64 * ALD;         // 128 x VLD (V transposed)
    float* Ps = Vt + 128 * VLD;         // 64 x PLD

    int tid = threadIdx.x;
    int lane = tid & 31, w = tid >> 5;
    int g = lane >> 2, tg = lane & 3;
    int wr = w * 16;
    int head = blockIdx.y;
    int qtile = gridDim.x - 1 - blockIdx.x;   // long blocks first
    int q0 = qtile * 64;

    const float* qbase = g_mixed + head * 384;
    const float* kbase = qbase + 128;
    const float* vbase = qbase + 256;
    const float scale = 0.08838834764831845f; // 1/sqrt(128)

    for (int e = tid; e < 64 * 32; e += 128) {
        int r = e >> 5, c4 = (e & 31) << 2;
        *(float4*)(Ks + r * ALD + c4) =
            *(const float4*)(qbase + (size_t)(q0 + r) * ROWSTRIDE + c4);
    }
    __syncthreads();
    uint32_t qf[16][4];
#pragma unroll
    for (int ks = 0; ks < 16; ks++) {
        const float* p0 = Ks + (wr + g) * ALD + ks * 8 + tg;
        const float* p1 = Ks + (wr + g + 8) * ALD + ks * 8 + tg;
        qf[ks][0] = __float_as_uint(p0[0]);
        qf[ks][1] = __float_as_uint(p1[0]);
        qf[ks][2] = __float_as_uint(p0[4]);
        qf[ks][3] = __float_as_uint(p1[4]);
    }

    float O[16][4];
#pragma unroll
    for (int jd = 0; jd < 16; jd++)
#pragma unroll
        for (int q = 0; q < 4; q++) O[jd][q] = 0.f;
    float m0r = -INFINITY, m1r = -INFINITY, l0 = 0.f, l1 = 0.f;

    int ntiles = qtile + 1;
    for (int tile = 0; tile < ntiles; tile++) {
        int t0 = tile * 64;
        __syncthreads();
        for (int e = tid; e < 64 * 32; e += 128) {
            int r = e >> 5, c4 = (e & 31) << 2;
            const float* src = kbase + (size_t)(t0 + r) * ROWSTRIDE + c4;
            *(float4*)(Ks + r * ALD + c4) = *(const float4*)src;
            float4 v = *(const float4*)(vbase + (size_t)(t0 + r) * ROWSTRIDE + c4);
            Vt[(c4 + 0) * VLD + r] = v.x;
            Vt[(c4 + 1) * VLD + r] = v.y;
            Vt[(c4 + 2) * VLD + r] = v.z;
            Vt[(c4 + 3) * VLD + r] = v.w;
        }
        __syncthreads();

        float s[8][4];
#pragma unroll
        for (int jn = 0; jn < 8; jn++)
#pragma unroll
            for (int q = 0; q < 4; q++) s[jn][q] = 0.f;
#pragma unroll
        for (int ks = 0; ks < 16; ks++) {
            int k8 = ks * 8;
#pragma unroll
            for (int jn = 0; jn < 8; jn++) {
                uint32_t b[2];
                const float* p = Ks + (jn * 8 + g) * ALD + k8 + tg;
                b[0] = __float_as_uint(p[0]);
                b[1] = __float_as_uint(p[4]);
                mma_tf32_16n8k8(s[jn], qf[ks], b);
            }
        }

#pragma unroll
        for (int jn = 0; jn < 8; jn++)
#pragma unroll
            for (int q = 0; q < 4; q++) s[jn][q] *= scale;
        if (tile == ntiles - 1) {
#pragma unroll
            for (int jn = 0; jn < 8; jn++) {
                int c0 = jn * 8 + 2 * tg, c1 = c0 + 1;
                int r0 = wr + g, r1 = wr + g + 8;
                if (c0 > r0) s[jn][0] = -1e30f;
                if (c1 > r0) s[jn][1] = -1e30f;
                if (c0 > r1) s[jn][2] = -1e30f;
                if (c1 > r1) s[jn][3] = -1e30f;
            }
        }

        float mx0 = -INFINITY, mx1 = -INFINITY;
#pragma unroll
        for (int jn = 0; jn < 8; jn++) {
            mx0 = fmaxf(mx0, fmaxf(s[jn][0], s[jn][1]));
            mx1 = fmaxf(mx1, fmaxf(s[jn][2], s[jn][3]));
        }
        mx0 = fmaxf(mx0, __shfl_xor_sync(0xffffffffu, mx0, 1));
        mx0 = fmaxf(mx0, __shfl_xor_sync(0xffffffffu, mx0, 2));
        mx1 = fmaxf(mx1, __shfl_xor_sync(0xffffffffu, mx1, 1));
        mx1 = fmaxf(mx1, __shfl_xor_sync(0xffffffffu, mx1, 2));

        float mn0 = fmaxf(m0r, mx0), mn1 = fmaxf(m1r, mx1);
        float al0 = __expf(m0r - mn0), al1 = __expf(m1r - mn1);
        m0r = mn0; m1r = mn1;

        float sum0 = 0.f, sum1 = 0.f;
#pragma unroll
        for (int jn = 0; jn < 8; jn++) {
            float p00 = __expf(s[jn][0] - m0r);
            float p01 = __expf(s[jn][1] - m0r);
            float p10 = __expf(s[jn][2] - m1r);
            float p11 = __expf(s[jn][3] - m1r);
            sum0 += p00 + p01;
            sum1 += p10 + p11;
            int cc = jn * 8 + 2 * tg;
            *(float2*)(Ps + (wr + g) * PLD + cc) =
                make_float2(tf32_rna(p00), tf32_rna(p01));
            *(float2*)(Ps + (wr + g + 8) * PLD + cc) =
                make_float2(tf32_rna(p10), tf32_rna(p11));
        }
        sum0 += __shfl_xor_sync(0xffffffffu, sum0, 1);
        sum0 += __shfl_xor_sync(0xffffffffu, sum0, 2);
        sum1 += __shfl_xor_sync(0xffffffffu, sum1, 1);
        sum1 += __shfl_xor_sync(0xffffffffu, sum1, 2);
        l0 = l0 * al0 + sum0;
        l1 = l1 * al1 + sum1;

#pragma unroll
        for (int jd = 0; jd < 16; jd++) {
            O[jd][0] *= al0; O[jd][1] *= al0;
            O[jd][2] *= al1; O[jd][3] *= al1;
        }
        __syncwarp();

#pragma unroll
        for (int ks = 0; ks < 8; ks++) {
            int k8 = ks * 8;
            uint32_t a[4];
            const float* pa0 = Ps + (wr + g) * PLD + k8 + tg;
            const float* pa1 = Ps + (wr + g + 8) * PLD + k8 + tg;
            a[0] = __float_as_uint(pa0[0]);
            a[1] = __float_as_uint(pa1[0]);
            a[2] = __float_as_uint(pa0[4]);
            a[3] = __float_as_uint(pa1[4]);
#pragma unroll
            for (int jd = 0; jd < 16; jd++) {
                uint32_t b[2];
                const float* p = Vt + (jd * 8 + g) * VLD + k8 + tg;
                b[0] = __float_as_uint(p[0]);
                b[1] = __float_as_uint(p[4]);
                mma_tf32_16n8k8(O[jd], a, b);
            }
        }
        __syncwarp();
    }

    float inv0 = 1.f / l0, inv1 = 1.f / l1;
#pragma unroll
    for (int jd = 0; jd < 16; jd++) {
        int col = head * HD + jd * 8 + 2 * tg;
        float* d0 = g_ctx + (size_t)(q0 + wr + g) * HID + col;
        float* d1 = g_ctx + (size_t)(q0 + wr + g + 8) * HID + col;
        *(float2*)d0 = make_float2(tf32_rna(O[jd][0] * inv0),
                                   tf32_rna(O[jd][1] * inv0));
        *(float2*)d1 = make_float2(tf32_rna(O[jd][2] * inv1),
                                   tf32_rna(O[jd][3] * inv1));
    }
}

// ---------------------------------------------------------------------------
extern "C" void kernel_launch(void* const* d_in, const int* in_sizes, int n_in,
                              void* d_out, int out_size)
{
    const float* hidden  = (const float*)d_in[0];
    const float* w_qkv   = (const float*)d_in[2];
    const float* b_qkv   = (const float*)d_in[3];
    const float* w_dense = (const float*)d_in[4];
    float* out = (float*)d_out;

    float *mixed, *ctx, *hid_t, *wqkv_t, *wdense_t;
    cudaGetSymbolAddress((void**)&mixed, g_mixed);
    cudaGetSymbolAddress((void**)&ctx, g_ctx);
    cudaGetSymbolAddress((void**)&hid_t, g_hid_t);
    cudaGetSymbolAddress((void**)&wqkv_t, g_wqkv_t);
    cudaGetSymbolAddress((void**)&wdense_t, g_wdense_t);

    cudaFuncSetAttribute(gemm_mma_kernel,
                         cudaFuncAttributeMaxDynamicSharedMemorySize, SMEM_GEMM);
    cudaFuncSetAttribute(attn_mma_kernel,
                         cudaFuncAttributeMaxDynamicSharedMemorySize, ATT_SMEM);

    // 0) round inputs to tf32
    {
        int n4 = SQ * HID / 4;
        cvt_tf32_kernel<<<(n4 + 255) / 256, 256>>>(hidden, hid_t, n4);
        int w4 = QKV_N * HID / 4;
        cvt_tf32_kernel<<<(w4 + 255) / 256, 256>>>(w_qkv, wqkv_t, w4);
        int d4 = HID * HID / 4;
        cvt_tf32_kernel<<<(d4 + 255) / 256, 256>>>(w_dense, wdense_t, d4);
    }
    // 1) QKV projection
    {
        dim3 grid(QKV_N / 128, SQ / 128);
        gemm_mma_kernel<<<grid, 128, SMEM_GEMM>>>(hid_t, wqkv_t, b_qkv, mixed,
                                                  QKV_N, HID);
    }
    // 2) rotary + tf32 rounding of q,k,v
    {
        int total = SQ * NHEAD * 64;
        rotary_kernel<<<(total + 255) / 256, 256>>>();
    }
    // 3) causal flash attention (tensor cores)
    {
        dim3 grid(SQ / 64, NHEAD);
        attn_mma_kernel<<<grid, 128, ATT_SMEM>>>();
    }
    // 4) dense
    {
        dim3 grid(HID / 128, SQ / 128);
        gemm_mma_kernel<<<grid, 128, SMEM_GEMM>>>(ctx, wdense_t, nullptr, out,
                                                  HID, HID);
    }
}

// round 12
// speedup vs baseline: 1.1233x; 1.1233x over previous
#include <cuda_runtime.h>
#include <math.h>
#include <cstdint>

#define SQ   2048
#define HID  2048
#define NHEAD 16
#define HD   128
#define QKV_N (3*HID)   // 6144
#define ROWSTRIDE 6144

// Scratch (device globals — no allocation allowed)
__device__ float g_mixed[(size_t)SQ * QKV_N];
__device__ float g_ctx[(size_t)SQ * HID];       // tf32-rounded
__device__ float g_hid_t[(size_t)SQ * HID];     // tf32-rounded hidden
__device__ float g_wqkv_t[(size_t)QKV_N * HID]; // tf32-rounded w_qkv
__device__ float g_wdense_t[(size_t)HID * HID]; // tf32-rounded w_dense

// ---------------------------------------------------------------------------
// Helpers
// ---------------------------------------------------------------------------
__device__ __forceinline__ uint32_t smem_u32(const void* p) {
    uint32_t a;
    asm("{ .reg .u64 t; cvta.to.shared.u64 t, %1; cvt.u32.u64 %0, t; }"
        : "=r"(a) : "l"(p));
    return a;
}
__device__ __forceinline__ void cp_async16(uint32_t d, const void* s) {
    asm volatile("cp.async.cg.shared.global [%0], [%1], 16;"
                 :: "r"(d), "l"(s) : "memory");
}
__device__ __forceinline__ float tf32_rna(float x) {
    uint32_t t;
    asm("cvt.rna.tf32.f32 %0, %1;" : "=r"(t) : "f"(x));
    return __uint_as_float(t);
}
// m16n8k8 tf32 MMA: D += A(16x8,row) * B(8x8,col)
__device__ __forceinline__ void mma_tf32_16n8k8(float* c, const uint32_t* a,
                                                const uint32_t* b) {
    asm volatile(
        "mma.sync.aligned.m16n8k8.row.col.f32.tf32.tf32.f32 "
        "{%0,%1,%2,%3}, {%4,%5,%6,%7}, {%8,%9}, {%0,%1,%2,%3};"
        : "+f"(c[0]), "+f"(c[1]), "+f"(c[2]), "+f"(c[3])
        : "r"(a[0]), "r"(a[1]), "r"(a[2]), "r"(a[3]), "r"(b[0]), "r"(b[1]));
}

// ---------------------------------------------------------------------------
// tf32 rounding kernel (fp32 -> tf32-rounded fp32)
// ---------------------------------------------------------------------------
__global__ void __launch_bounds__(256) cvt_tf32_kernel(
    const float* __restrict__ in, float* __restrict__ out, int n4)
{
    int i = blockIdx.x * blockDim.x + threadIdx.x;
    if (i >= n4) return;
    float4 v = ((const float4*)in)[i];
    v.x = tf32_rna(v.x); v.y = tf32_rna(v.y);
    v.z = tf32_rna(v.z); v.w = tf32_rna(v.w);
    ((float4*)out)[i] = v;
}

// ---------------------------------------------------------------------------
// mma.sync tf32 NT GEMM: C[M,N] = A[M,K]*B[N,K]^T (+bias)
// R8 shape (256 threads, 8 warps, 64x32 warp tile, 3-stage cp.async) plus
// register double-buffering of fragments: load ks+1 frags during ks MMAs.
// __launch_bounds__(256,2) pins regs <=128 so 2 CTAs/SM (16 warps) survive.
// ---------------------------------------------------------------------------
#define BK 32
#define PADK 36
#define STAGE_F (2 * 128 * PADK)
#define GSTAGES 3
#define SMEM_GEMM (GSTAGES * STAGE_F * 4)

__global__ void __launch_bounds__(256, 2)
gemm_mma_kernel(const float* __restrict__ A, const float* __restrict__ Bw,
                const float* __restrict__ bias, float* __restrict__ C,
                int N, int K)
{
    extern __shared__ float sm[];
    int tid = threadIdx.x;
    int lane = tid & 31, wid = tid >> 5;
    int g = lane >> 2, tg = lane & 3;
    int wm = wid & 1, wn = wid >> 1;        // 2x4 warps, 64x32 each
    int m0 = blockIdx.y * 128, n0 = blockIdx.x * 128;

    float acc[4][4][4];
#pragma unroll
    for (int im = 0; im < 4; im++)
#pragma unroll
        for (int jn = 0; jn < 4; jn++)
#pragma unroll
            for (int q = 0; q < 4; q++) acc[im][jn][q] = 0.f;

    const int nk = K / BK;
    int frow = tid >> 1;
    int fcb  = (tid & 1) * 4;
    const float* gArow = A  + (size_t)(m0 + frow) * K + fcb * 4;
    const float* gBrow = Bw + (size_t)(n0 + frow) * K + fcb * 4;

    auto fill = [&](int j) {
        int slot = j % GSTAGES;
        float* dA = sm + slot * STAGE_F + frow * PADK + fcb * 4;
        float* dB = dA + 128 * PADK;
        const float* sA = gArow + j * BK;
        const float* sB = gBrow + j * BK;
#pragma unroll
        for (int q = 0; q < 4; q++) {
            cp_async16(smem_u32(dA + q * 4), sA + q * 4);
            cp_async16(smem_u32(dB + q * 4), sB + q * 4);
        }
        asm volatile("cp.async.commit_group;" ::: "memory");
    };

    fill(0);
    fill(1);

    for (int i = 0; i < nk; i++) {
        asm volatile("cp.async.wait_group 1;" ::: "memory");
        __syncthreads();
        if (i + 2 < nk) fill(i + 2);

        int slot = i % GSTAGES;
        const float* As = sm + slot * STAGE_F + (wm * 64) * PADK;
        const float* Bs = sm + slot * STAGE_F + 128 * PADK + (wn * 32) * PADK;

        // fragment double-buffer: load ks+1 while MMAs of ks run
        uint32_t a2[2][4][4], b2[2][4][2];

        auto ldfr = [&](int ks, int buf) {
            int k8 = ks * 8;
#pragma unroll
            for (int im = 0; im < 4; im++) {
                const float* p = As + (im * 16 + g) * PADK + k8 + tg;
                a2[buf][im][0] = __float_as_uint(p[0]);
                a2[buf][im][1] = __float_as_uint(p[8 * PADK]);
                a2[buf][im][2] = __float_as_uint(p[4]);
                a2[buf][im][3] = __float_as_uint(p[8 * PADK + 4]);
            }
#pragma unroll
            for (int jn = 0; jn < 4; jn++) {
                const float* p = Bs + (jn * 8 + g) * PADK + k8 + tg;
                b2[buf][jn][0] = __float_as_uint(p[0]);
                b2[buf][jn][1] = __float_as_uint(p[4]);
            }
        };

        ldfr(0, 0);
#pragma unroll
        for (int ks = 0; ks < 4; ks++) {
            if (ks < 3) ldfr(ks + 1, (ks + 1) & 1);
            int cur = ks & 1;
#pragma unroll
            for (int im = 0; im < 4; im++)
#pragma unroll
                for (int jn = 0; jn < 4; jn++)
                    mma_tf32_16n8k8(acc[im][jn], a2[cur][im], b2[cur][jn]);
        }
    }

#pragma unroll
    for (int im = 0; im < 4; im++) {
#pragma unroll
        for (int jn = 0; jn < 4; jn++) {
            int mrow = m0 + wm * 64 + im * 16 + g;
            int ncol = n0 + wn * 32 + jn * 8 + 2 * tg;
            float b0 = 0.f, b1 = 0.f;
            if (bias) { b0 = bias[ncol]; b1 = bias[ncol + 1]; }
            float2 v0 = make_float2(acc[im][jn][0] + b0, acc[im][jn][1] + b1);
            float2 v1 = make_float2(acc[im][jn][2] + b0, acc[im][jn][3] + b1);
            *(float2*)(C + (size_t)mrow * N + ncol) = v0;
            *(float2*)(C + (size_t)(mrow + 8) * N + ncol) = v1;
        }
    }
}

// ---------------------------------------------------------------------------
// Rotary (in place on g_mixed q,k) + tf32-round q,k,v for the attention MMAs
// ---------------------------------------------------------------------------
__global__ void __launch_bounds__(256) rotary_kernel()
{
    int idx = blockIdx.x * blockDim.x + threadIdx.x;
    if (idx >= SQ * NHEAD * 64) return;
    int j = idx & 63;
    int n = (idx >> 6) & (NHEAD - 1);
    int s = idx >> 10;

    float invf = powf(10000.0f, -(float)(2 * j) / 128.0f);
    float th = (float)s * invf;
    float c = cosf(th), sn = sinf(th);

    float* row = g_mixed + (size_t)s * ROWSTRIDE + n * 384;
    float q1 = row[j], q2 = row[j + 64];
    row[j]      = tf32_rna(q1 * c - q2 * sn);
    row[j + 64] = tf32_rna(q2 * c + q1 * sn);
    float k1 = row[128 + j], k2 = row[128 + j + 64];
    row[128 + j]      = tf32_rna(k1 * c - k2 * sn);
    row[128 + j + 64] = tf32_rna(k2 * c + k1 * sn);
    // round V (2 elements per thread to cover 128)
    row[256 + j]      = tf32_rna(row[256 + j]);
    row[256 + j + 64] = tf32_rna(row[256 + j + 64]);
}

// ---------------------------------------------------------------------------
// Flash attention (causal) on mma.sync tf32 (unchanged from R8 WIN).
// 128 threads = 4 warps, each warp owns 16 query rows. Br=Bc=64, D=128.
// ---------------------------------------------------------------------------
#define ALD 132   // K/Q smem row stride (floats)
#define VLD 68    // V^T smem row stride
#define PLD 76    // P smem row stride
#define ATT_SMEM ((64*ALD + 128*VLD + 64*PLD) * 4)

__global__ void __launch_bounds__(128) attn_mma_kernel()
{
    extern __shared__ float smf[];
    float* Ks = smf;                    // 64 x ALD (also Q staging)
    float* Vt = smf + 64 * ALD;         // 128 x VLD (V transposed)
    float* Ps = Vt + 128 * VLD;         // 64 x PLD

    int tid = threadIdx.x;
    int lane = tid & 31, w = tid >> 5;
    int g = lane >> 2, tg = lane & 3;
    int wr = w * 16;
    int head = blockIdx.y;
    int qtile = gridDim.x - 1 - blockIdx.x;   // long blocks first
    int q0 = qtile * 64;

    const float* qbase = g_mixed + head * 384;
    const float* kbase = qbase + 128;
    const float* vbase = qbase + 256;
    const float scale = 0.08838834764831845f; // 1/sqrt(128)

    for (int e = tid; e < 64 * 32; e += 128) {
        int r = e >> 5, c4 = (e & 31) << 2;
        *(float4*)(Ks + r * ALD + c4) =
            *(const float4*)(qbase + (size_t)(q0 + r) * ROWSTRIDE + c4);
    }
    __syncthreads();
    uint32_t qf[16][4];
#pragma unroll
    for (int ks = 0; ks < 16; ks++) {
        const float* p0 = Ks + (wr + g) * ALD + ks * 8 + tg;
        const float* p1 = Ks + (wr + g + 8) * ALD + ks * 8 + tg;
        qf[ks][0] = __float_as_uint(p0[0]);
        qf[ks][1] = __float_as_uint(p1[0]);
        qf[ks][2] = __float_as_uint(p0[4]);
        qf[ks][3] = __float_as_uint(p1[4]);
    }

    float O[16][4];
#pragma unroll
    for (int jd = 0; jd < 16; jd++)
#pragma unroll
        for (int q = 0; q < 4; q++) O[jd][q] = 0.f;
    float m0r = -INFINITY, m1r = -INFINITY, l0 = 0.f, l1 = 0.f;

    int ntiles = qtile + 1;
    for (int tile = 0; tile < ntiles; tile++) {
        int t0 = tile * 64;
        __syncthreads();
        for (int e = tid; e < 64 * 32; e += 128) {
            int r = e >> 5, c4 = (e & 31) << 2;
            const float* src = kbase + (size_t)(t0 + r) * ROWSTRIDE + c4;
            *(float4*)(Ks + r * ALD + c4) = *(const float4*)src;
            float4 v = *(const float4*)(vbase + (size_t)(t0 + r) * ROWSTRIDE + c4);
            Vt[(c4 + 0) * VLD + r] = v.x;
            Vt[(c4 + 1) * VLD + r] = v.y;
            Vt[(c4 + 2) * VLD + r] = v.z;
            Vt[(c4 + 3) * VLD + r] = v.w;
        }
        __syncthreads();

        float s[8][4];
#pragma unroll
        for (int jn = 0; jn < 8; jn++)
#pragma unroll
            for (int q = 0; q < 4; q++) s[jn][q] = 0.f;
#pragma unroll
        for (int ks = 0; ks < 16; ks++) {
            int k8 = ks * 8;
#pragma unroll
            for (int jn = 0; jn < 8; jn++) {
                uint32_t b[2];
                const float* p = Ks + (jn * 8 + g) * ALD + k8 + tg;
                b[0] = __float_as_uint(p[0]);
                b[1] = __float_as_uint(p[4]);
                mma_tf32_16n8k8(s[jn], qf[ks], b);
            }
        }

#pragma unroll
        for (int jn = 0; jn < 8; jn++)
#pragma unroll
            for (int q = 0; q < 4; q++) s[jn][q] *= scale;
        if (tile == ntiles - 1) {
#pragma unroll
            for (int jn = 0; jn < 8; jn++) {
                int c0 = jn * 8 + 2 * tg, c1 = c0 + 1;
                int r0 = wr + g, r1 = wr + g + 8;
                if (c0 > r0) s[jn][0] = -1e30f;
                if (c1 > r0) s[jn][1] = -1e30f;
                if (c0 > r1) s[jn][2] = -1e30f;
                if (c1 > r1) s[jn][3] = -1e30f;
            }
        }

        float mx0 = -INFINITY, mx1 = -INFINITY;
#pragma unroll
        for (int jn = 0; jn < 8; jn++) {
            mx0 = fmaxf(mx0, fmaxf(s[jn][0], s[jn][1]));
            mx1 = fmaxf(mx1, fmaxf(s[jn][2], s[jn][3]));
        }
        mx0 = fmaxf(mx0, __shfl_xor_sync(0xffffffffu, mx0, 1));
        mx0 = fmaxf(mx0, __shfl_xor_sync(0xffffffffu, mx0, 2));
        mx1 = fmaxf(mx1, __shfl_xor_sync(0xffffffffu, mx1, 1));
        mx1 = fmaxf(mx1, __shfl_xor_sync(0xffffffffu, mx1, 2));

        float mn0 = fmaxf(m0r, mx0), mn1 = fmaxf(m1r, mx1);
        float al0 = __expf(m0r - mn0), al1 = __expf(m1r - mn1);
        m0r = mn0; m1r = mn1;

        float sum0 = 0.f, sum1 = 0.f;
#pragma unroll
        for (int jn = 0; jn < 8; jn++) {
            float p00 = __expf(s[jn][0] - m0r);
            float p01 = __expf(s[jn][1] - m0r);
            float p10 = __expf(s[jn][2] - m1r);
            float p11 = __expf(s[jn][3] - m1r);
            sum0 += p00 + p01;
            sum1 += p10 + p11;
            int cc = jn * 8 + 2 * tg;
            *(float2*)(Ps + (wr + g) * PLD + cc) =
                make_float2(tf32_rna(p00), tf32_rna(p01));
            *(float2*)(Ps + (wr + g + 8) * PLD + cc) =
                make_float2(tf32_rna(p10), tf32_rna(p11));
        }
        sum0 += __shfl_xor_sync(0xffffffffu, sum0, 1);
        sum0 += __shfl_xor_sync(0xffffffffu, sum0, 2);
        sum1 += __shfl_xor_sync(0xffffffffu, sum1, 1);
        sum1 += __shfl_xor_sync(0xffffffffu, sum1, 2);
        l0 = l0 * al0 + sum0;
        l1 = l1 * al1 + sum1;

#pragma unroll
        for (int jd = 0; jd < 16; jd++) {
            O[jd][0] *= al0; O[jd][1] *= al0;
            O[jd][2] *= al1; O[jd][3] *= al1;
        }
        __syncwarp();

#pragma unroll
        for (int ks = 0; ks < 8; ks++) {
            int k8 = ks * 8;
            uint32_t a[4];
            const float* pa0 = Ps + (wr + g) * PLD + k8 + tg;
            const float* pa1 = Ps + (wr + g + 8) * PLD + k8 + tg;
            a[0] = __float_as_uint(pa0[0]);
            a[1] = __float_as_uint(pa1[0]);
            a[2] = __float_as_uint(pa0[4]);
            a[3] = __float_as_uint(pa1[4]);
#pragma unroll
            for (int jd = 0; jd < 16; jd++) {
                uint32_t b[2];
                const float* p = Vt + (jd * 8 + g) * VLD + k8 + tg;
                b[0] = __float_as_uint(p[0]);
                b[1] = __float_as_uint(p[4]);
                mma_tf32_16n8k8(O[jd], a, b);
            }
        }
        __syncwarp();
    }

    float inv0 = 1.f / l0, inv1 = 1.f / l1;
#pragma unroll
    for (int jd = 0; jd < 16; jd++) {
        int col = head * HD + jd * 8 + 2 * tg;
        float* d0 = g_ctx + (size_t)(q0 + wr + g) * HID + col;
        float* d1 = g_ctx + (size_t)(q0 + wr + g + 8) * HID + col;
        *(float2*)d0 = make_float2(tf32_rna(O[jd][0] * inv0),
                                   tf32_rna(O[jd][1] * inv0));
        *(float2*)d1 = make_float2(tf32_rna(O[jd][2] * inv1),
                                   tf32_rna(O[jd][3] * inv1));
    }
}

// ---------------------------------------------------------------------------
extern "C" void kernel_launch(void* const* d_in, const int* in_sizes, int n_in,
                              void* d_out, int out_size)
{
    const float* hidden  = (const float*)d_in[0];
    const float* w_qkv   = (const float*)d_in[2];
    const float* b_qkv   = (const float*)d_in[3];
    const float* w_dense = (const float*)d_in[4];
    float* out = (float*)d_out;

    float *mixed, *ctx, *hid_t, *wqkv_t, *wdense_t;
    cudaGetSymbolAddress((void**)&mixed, g_mixed);
    cudaGetSymbolAddress((void**)&ctx, g_ctx);
    cudaGetSymbolAddress((void**)&hid_t, g_hid_t);
    cudaGetSymbolAddress((void**)&wqkv_t, g_wqkv_t);
    cudaGetSymbolAddress((void**)&wdense_t, g_wdense_t);

    cudaFuncSetAttribute(gemm_mma_kernel,
                         cudaFuncAttributeMaxDynamicSharedMemorySize, SMEM_GEMM);
    cudaFuncSetAttribute(attn_mma_kernel,
                         cudaFuncAttributeMaxDynamicSharedMemorySize, ATT_SMEM);

    // 0) round inputs to tf32
    {
        int n4 = SQ * HID / 4;
        cvt_tf32_kernel<<<(n4 + 255) / 256, 256>>>(hidden, hid_t, n4);
        int w4 = QKV_N * HID / 4;
        cvt_tf32_kernel<<<(w4 + 255) / 256, 256>>>(w_qkv, wqkv_t, w4);
        int d4 = HID * HID / 4;
        cvt_tf32_kernel<<<(d4 + 255) / 256, 256>>>(w_dense, wdense_t, d4);
    }
    // 1) QKV projection
    {
        dim3 grid(QKV_N / 128, SQ / 128);
        gemm_mma_kernel<<<grid, 256, SMEM_GEMM>>>(hid_t, wqkv_t, b_qkv, mixed,
                                                  QKV_N, HID);
    }
    // 2) rotary + tf32 rounding of q,k,v
    {
        int total = SQ * NHEAD * 64;
        rotary_kernel<<<(total + 255) / 256, 256>>>();
    }
    // 3) causal flash attention (tensor cores)
    {
        dim3 grid(SQ / 64, NHEAD);
        attn_mma_kernel<<<grid, 128, ATT_SMEM>>>();
    }
    // 4) dense (256 threads — fixed from stale 128-thread launch)
    {
        dim3 grid(HID / 128, SQ / 128);
        gemm_mma_kernel<<<grid, 256, SMEM_GEMM>>>(ctx, wdense_t, nullptr, out,
                                                  HID, HID);
    }
}

// round 14
// speedup vs baseline: 1.3641x; 1.2144x over previous
#include <cuda_runtime.h>
#include <math.h>
#include <cstdint>

#define SQ   2048
#define HID  2048
#define NHEAD 16
#define HD   128
#define QKV_N (3*HID)   // 6144
#define ROWSTRIDE 6144

// Scratch (device globals — no allocation allowed)
__device__ float g_mixed[(size_t)SQ * QKV_N];
__device__ float g_ctx[(size_t)SQ * HID];       // tf32-rounded
__device__ float g_hid_t[(size_t)SQ * HID];     // tf32-rounded hidden
__device__ float g_wqkv_t[(size_t)QKV_N * HID]; // tf32-rounded w_qkv
__device__ float g_wdense_t[(size_t)HID * HID]; // tf32-rounded w_dense

// ---------------------------------------------------------------------------
// Helpers
// ---------------------------------------------------------------------------
__device__ __forceinline__ uint32_t smem_u32(const void* p) {
    uint32_t a;
    asm("{ .reg .u64 t; cvta.to.shared.u64 t, %1; cvt.u32.u64 %0, t; }"
        : "=r"(a) : "l"(p));
    return a;
}
__device__ __forceinline__ void cp_async16(uint32_t d, const void* s) {
    asm volatile("cp.async.cg.shared.global [%0], [%1], 16;"
                 :: "r"(d), "l"(s) : "memory");
}
__device__ __forceinline__ float tf32_rna(float x) {
    uint32_t t;
    asm("cvt.rna.tf32.f32 %0, %1;" : "=r"(t) : "f"(x));
    return __uint_as_float(t);
}
// m16n8k8 tf32 MMA: D += A(16x8,row) * B(8x8,col)
__device__ __forceinline__ void mma_tf32_16n8k8(float* c, const uint32_t* a,
                                                const uint32_t* b) {
    asm volatile(
        "mma.sync.aligned.m16n8k8.row.col.f32.tf32.tf32.f32 "
        "{%0,%1,%2,%3}, {%4,%5,%6,%7}, {%8,%9}, {%0,%1,%2,%3};"
        : "+f"(c[0]), "+f"(c[1]), "+f"(c[2]), "+f"(c[3])
        : "r"(a[0]), "r"(a[1]), "r"(a[2]), "r"(a[3]), "r"(b[0]), "r"(b[1]));
}

// ---------------------------------------------------------------------------
// tf32 rounding kernel (fp32 -> tf32-rounded fp32)
// ---------------------------------------------------------------------------
__global__ void __launch_bounds__(256) cvt_tf32_kernel(
    const float* __restrict__ in, float* __restrict__ out, int n4)
{
    int i = blockIdx.x * blockDim.x + threadIdx.x;
    if (i >= n4) return;
    float4 v = ((const float4*)in)[i];
    v.x = tf32_rna(v.x); v.y = tf32_rna(v.y);
    v.z = tf32_rna(v.z); v.w = tf32_rna(v.w);
    ((float4*)out)[i] = v;
}

// ---------------------------------------------------------------------------
// mma.sync tf32 NT GEMM: C[M,N] = A[M,K]*B[N,K]^T (+bias)
// CTA tile 256x128, 512 threads = 16 warps (4x4 grid of 64x32 warp tiles).
// 25% less fill traffic per output than 128x128; same per-warp reg budget.
// BK=32, 3-stage cp.async pipeline, fragment double-buffer in registers.
// ---------------------------------------------------------------------------
#define BM 256
#define BN 128
#define BK 32
#define PADK 36
#define STAGE_F ((BM + BN) * PADK)
#define GSTAGES 3
#define SMEM_GEMM (GSTAGES * STAGE_F * 4)

__global__ void __launch_bounds__(512, 1)
gemm_mma_kernel(const float* __restrict__ A, const float* __restrict__ Bw,
                const float* __restrict__ bias, float* __restrict__ C,
                int N, int K)
{
    extern __shared__ float sm[];
    int tid = threadIdx.x;
    int lane = tid & 31, wid = tid >> 5;
    int g = lane >> 2, tg = lane & 3;
    int wm = wid & 3, wn = wid >> 2;        // 4x4 warps, 64x32 each
    int m0 = blockIdx.y * BM, n0 = blockIdx.x * BN;

    float acc[4][4][4];
#pragma unroll
    for (int im = 0; im < 4; im++)
#pragma unroll
        for (int jn = 0; jn < 4; jn++)
#pragma unroll
            for (int q = 0; q < 4; q++) acc[im][jn][q] = 0.f;

    const int nk = K / BK;

    // Fill mapping: thread owns smem rows r0+64q (q=0..5), 16B chunk jc.
    // Rows 0..255 = A tile, rows 256..383 = B tile. Coalesced across tid.
    int r0 = tid >> 3;
    int jc = (tid & 7) * 4;
    const float* gsrc[6];
    uint32_t soff[6];
#pragma unroll
    for (int q = 0; q < 6; q++) {
        int row = r0 + 64 * q;
        gsrc[q] = (row < BM)
                ? A  + (size_t)(m0 + row) * K + jc
                : Bw + (size_t)(n0 + row - BM) * K + jc;
        soff[q] = (uint32_t)(row * PADK + jc);
    }

    auto fill = [&](int j) {
        int slot = j % GSTAGES;
        uint32_t sbase = smem_u32(sm + slot * STAGE_F);
        int koff = j * BK;
#pragma unroll
        for (int q = 0; q < 6; q++)
            cp_async16(sbase + soff[q] * 4, gsrc[q] + koff);
        asm volatile("cp.async.commit_group;" ::: "memory");
    };

    fill(0);
    fill(1);

    for (int i = 0; i < nk; i++) {
        asm volatile("cp.async.wait_group 1;" ::: "memory");
        __syncthreads();
        if (i + 2 < nk) fill(i + 2);

        int slot = i % GSTAGES;
        const float* As = sm + slot * STAGE_F + (wm * 64) * PADK;
        const float* Bs = sm + slot * STAGE_F + (BM + wn * 32) * PADK;

        uint32_t a2[2][4][4], b2[2][4][2];

        auto ldfr = [&](int ks, int buf) {
            int k8 = ks * 8;
#pragma unroll
            for (int im = 0; im < 4; im++) {
                const float* p = As + (im * 16 + g) * PADK + k8 + tg;
                a2[buf][im][0] = __float_as_uint(p[0]);
                a2[buf][im][1] = __float_as_uint(p[8 * PADK]);
                a2[buf][im][2] = __float_as_uint(p[4]);
                a2[buf][im][3] = __float_as_uint(p[8 * PADK + 4]);
            }
#pragma unroll
            for (int jn = 0; jn < 4; jn++) {
                const float* p = Bs + (jn * 8 + g) * PADK + k8 + tg;
                b2[buf][jn][0] = __float_as_uint(p[0]);
                b2[buf][jn][1] = __float_as_uint(p[4]);
            }
        };

        ldfr(0, 0);
#pragma unroll
        for (int ks = 0; ks < 4; ks++) {
            if (ks < 3) ldfr(ks + 1, (ks + 1) & 1);
            int cur = ks & 1;
#pragma unroll
            for (int im = 0; im < 4; im++)
#pragma unroll
                for (int jn = 0; jn < 4; jn++)
                    mma_tf32_16n8k8(acc[im][jn], a2[cur][im], b2[cur][jn]);
        }
    }

#pragma unroll
    for (int im = 0; im < 4; im++) {
#pragma unroll
        for (int jn = 0; jn < 4; jn++) {
            int mrow = m0 + wm * 64 + im * 16 + g;
            int ncol = n0 + wn * 32 + jn * 8 + 2 * tg;
            float b0 = 0.f, b1 = 0.f;
            if (bias) { b0 = bias[ncol]; b1 = bias[ncol + 1]; }
            float2 v0 = make_float2(acc[im][jn][0] + b0, acc[im][jn][1] + b1);
            float2 v1 = make_float2(acc[im][jn][2] + b0, acc[im][jn][3] + b1);
            *(float2*)(C + (size_t)mrow * N + ncol) = v0;
            *(float2*)(C + (size_t)(mrow + 8) * N + ncol) = v1;
        }
    }
}

// ---------------------------------------------------------------------------
// Rotary (in place on g_mixed q,k) + tf32-round q,k,v for the attention MMAs
// ---------------------------------------------------------------------------
__global__ void __launch_bounds__(256) rotary_kernel()
{
    int idx = blockIdx.x * blockDim.x + threadIdx.x;
    if (idx >= SQ * NHEAD * 64) return;
    int j = idx & 63;
    int n = (idx >> 6) & (NHEAD - 1);
    int s = idx >> 10;

    float invf = powf(10000.0f, -(float)(2 * j) / 128.0f);
    float th = (float)s * invf;
    float c = cosf(th), sn = sinf(th);

    float* row = g_mixed + (size_t)s * ROWSTRIDE + n * 384;
    float q1 = row[j], q2 = row[j + 64];
    row[j]      = tf32_rna(q1 * c - q2 * sn);
    row[j + 64] = tf32_rna(q2 * c + q1 * sn);
    float k1 = row[128 + j], k2 = row[128 + j + 64];
    row[128 + j]      = tf32_rna(k1 * c - k2 * sn);
    row[128 + j + 64] = tf32_rna(k2 * c + k1 * sn);
    // round V (2 elements per thread to cover 128)
    row[256 + j]      = tf32_rna(row[256 + j]);
    row[256 + j + 64] = tf32_rna(row[256 + j + 64]);
}

// ---------------------------------------------------------------------------
// Flash attention (causal) on mma.sync tf32 (unchanged from R8 WIN).
// 128 threads = 4 warps, each warp owns 16 query rows. Br=Bc=64, D=128.
// ---------------------------------------------------------------------------
#define ALD 132   // K/Q smem row stride (floats)
#define VLD 68    // V^T smem row stride
#define PLD 76    // P smem row stride
#define ATT_SMEM ((64*ALD + 128*VLD + 64*PLD) * 4)

__global__ void __launch_bounds__(128) attn_mma_kernel()
{
    extern __shared__ float smf[];
    float* Ks = smf;                    // 64 x ALD (also Q staging)
    float* Vt = smf + 64 * ALD;         // 128 x VLD (V transposed)
    float* Ps = Vt + 128 * VLD;         // 64 x PLD

    int tid = threadIdx.x;
    int lane = tid & 31, w = tid >> 5;
    int g = lane >> 2, tg = lane & 3;
    int wr = w * 16;
    int head = blockIdx.y;
    int qtile = gridDim.x - 1 - blockIdx.x;   // long blocks first
    int q0 = qtile * 64;

    const float* qbase = g_mixed + head * 384;
    const float* kbase = qbase + 128;
    const float* vbase = qbase + 256;
    const float scale = 0.08838834764831845f; // 1/sqrt(128)

    for (int e = tid; e < 64 * 32; e += 128) {
        int r = e >> 5, c4 = (e & 31) << 2;
        *(float4*)(Ks + r * ALD + c4) =
            *(const float4*)(qbase + (size_t)(q0 + r) * ROWSTRIDE + c4);
    }
    __syncthreads();
    uint32_t qf[16][4];
#pragma unroll
    for (int ks = 0; ks < 16; ks++) {
        const float* p0 = Ks + (wr + g) * ALD + ks * 8 + tg;
        const float* p1 = Ks + (wr + g + 8) * ALD + ks * 8 + tg;
        qf[ks][0] = __float_as_uint(p0[0]);
        qf[ks][1] = __float_as_uint(p1[0]);
        qf[ks][2] = __float_as_uint(p0[4]);
        qf[ks][3] = __float_as_uint(p1[4]);
    }

    float O[16][4];
#pragma unroll
    for (int jd = 0; jd < 16; jd++)
#pragma unroll
        for (int q = 0; q < 4; q++) O[jd][q] = 0.f;
    float m0r = -INFINITY, m1r = -INFINITY, l0 = 0.f, l1 = 0.f;

    int ntiles = qtile + 1;
    for (int tile = 0; tile < ntiles; tile++) {
        int t0 = tile * 64;
        __syncthreads();
        for (int e = tid; e < 64 * 32; e += 128) {
            int r = e >> 5, c4 = (e & 31) << 2;
            const float* src = kbase + (size_t)(t0 + r) * ROWSTRIDE + c4;
            *(float4*)(Ks + r * ALD + c4) = *(const float4*)src;
            float4 v = *(const float4*)(vbase + (size_t)(t0 + r) * ROWSTRIDE + c4);
            Vt[(c4 + 0) * VLD + r] = v.x;
            Vt[(c4 + 1) * VLD + r] = v.y;
            Vt[(c4 + 2) * VLD + r] = v.z;
            Vt[(c4 + 3) * VLD + r] = v.w;
        }
        __syncthreads();

        float s[8][4];
#pragma unroll
        for (int jn = 0; jn < 8; jn++)
#pragma unroll
            for (int q = 0; q < 4; q++) s[jn][q] = 0.f;
#pragma unroll
        for (int ks = 0; ks < 16; ks++) {
            int k8 = ks * 8;
#pragma unroll
            for (int jn = 0; jn < 8; jn++) {
                uint32_t b[2];
                const float* p = Ks + (jn * 8 + g) * ALD + k8 + tg;
                b[0] = __float_as_uint(p[0]);
                b[1] = __float_as_uint(p[4]);
                mma_tf32_16n8k8(s[jn], qf[ks], b);
            }
        }

#pragma unroll
        for (int jn = 0; jn < 8; jn++)
#pragma unroll
            for (int q = 0; q < 4; q++) s[jn][q] *= scale;
        if (tile == ntiles - 1) {
#pragma unroll
            for (int jn = 0; jn < 8; jn++) {
                int c0 = jn * 8 + 2 * tg, c1 = c0 + 1;
                int r0 = wr + g, r1 = wr + g + 8;
                if (c0 > r0) s[jn][0] = -1e30f;
                if (c1 > r0) s[jn][1] = -1e30f;
                if (c0 > r1) s[jn][2] = -1e30f;
                if (c1 > r1) s[jn][3] = -1e30f;
            }
        }

        float mx0 = -INFINITY, mx1 = -INFINITY;
#pragma unroll
        for (int jn = 0; jn < 8; jn++) {
            mx0 = fmaxf(mx0, fmaxf(s[jn][0], s[jn][1]));
            mx1 = fmaxf(mx1, fmaxf(s[jn][2], s[jn][3]));
        }
        mx0 = fmaxf(mx0, __shfl_xor_sync(0xffffffffu, mx0, 1));
        mx0 = fmaxf(mx0, __shfl_xor_sync(0xffffffffu, mx0, 2));
        mx1 = fmaxf(mx1, __shfl_xor_sync(0xffffffffu, mx1, 1));
        mx1 = fmaxf(mx1, __shfl_xor_sync(0xffffffffu, mx1, 2));

        float mn0 = fmaxf(m0r, mx0), mn1 = fmaxf(m1r, mx1);
        float al0 = __expf(m0r - mn0), al1 = __expf(m1r - mn1);
        m0r = mn0; m1r = mn1;

        float sum0 = 0.f, sum1 = 0.f;
#pragma unroll
        for (int jn = 0; jn < 8; jn++) {
            float p00 = __expf(s[jn][0] - m0r);
            float p01 = __expf(s[jn][1] - m0r);
            float p10 = __expf(s[jn][2] - m1r);
            float p11 = __expf(s[jn][3] - m1r);
            sum0 += p00 + p01;
            sum1 += p10 + p11;
            int cc = jn * 8 + 2 * tg;
            *(float2*)(Ps + (wr + g) * PLD + cc) =
                make_float2(tf32_rna(p00), tf32_rna(p01));
            *(float2*)(Ps + (wr + g + 8) * PLD + cc) =
                make_float2(tf32_rna(p10), tf32_rna(p11));
        }
        sum0 += __shfl_xor_sync(0xffffffffu, sum0, 1);
        sum0 += __shfl_xor_sync(0xffffffffu, sum0, 2);
        sum1 += __shfl_xor_sync(0xffffffffu, sum1, 1);
        sum1 += __shfl_xor_sync(0xffffffffu, sum1, 2);
        l0 = l0 * al0 + sum0;
        l1 = l1 * al1 + sum1;

#pragma unroll
        for (int jd = 0; jd < 16; jd++) {
            O[jd][0] *= al0; O[jd][1] *= al0;
            O[jd][2] *= al1; O[jd][3] *= al1;
        }
        __syncwarp();

#pragma unroll
        for (int ks = 0; ks < 8; ks++) {
            int k8 = ks * 8;
            uint32_t a[4];
            const float* pa0 = Ps + (wr + g) * PLD + k8 + tg;
            const float* pa1 = Ps + (wr + g + 8) * PLD + k8 + tg;
            a[0] = __float_as_uint(pa0[0]);
            a[1] = __float_as_uint(pa1[0]);
            a[2] = __float_as_uint(pa0[4]);
            a[3] = __float_as_uint(pa1[4]);
#pragma unroll
            for (int jd = 0; jd < 16; jd++) {
                uint32_t b[2];
                const float* p = Vt + (jd * 8 + g) * VLD + k8 + tg;
                b[0] = __float_as_uint(p[0]);
                b[1] = __float_as_uint(p[4]);
                mma_tf32_16n8k8(O[jd], a, b);
            }
        }
        __syncwarp();
    }

    float inv0 = 1.f / l0, inv1 = 1.f / l1;
#pragma unroll
    for (int jd = 0; jd < 16; jd++) {
        int col = head * HD + jd * 8 + 2 * tg;
        float* d0 = g_ctx + (size_t)(q0 + wr + g) * HID + col;
        float* d1 = g_ctx + (size_t)(q0 + wr + g + 8) * HID + col;
        *(float2*)d0 = make_float2(tf32_rna(O[jd][0] * inv0),
                                   tf32_rna(O[jd][1] * inv0));
        *(float2*)d1 = make_float2(tf32_rna(O[jd][2] * inv1),
                                   tf32_rna(O[jd][3] * inv1));
    }
}

// ---------------------------------------------------------------------------
extern "C" void kernel_launch(void* const* d_in, const int* in_sizes, int n_in,
                              void* d_out, int out_size)
{
    const float* hidden  = (const float*)d_in[0];
    const float* w_qkv   = (const float*)d_in[2];
    const float* b_qkv   = (const float*)d_in[3];
    const float* w_dense = (const float*)d_in[4];
    float* out = (float*)d_out;

    float *mixed, *ctx, *hid_t, *wqkv_t, *wdense_t;
    cudaGetSymbolAddress((void**)&mixed, g_mixed);
    cudaGetSymbolAddress((void**)&ctx, g_ctx);
    cudaGetSymbolAddress((void**)&hid_t, g_hid_t);
    cudaGetSymbolAddress((void**)&wqkv_t, g_wqkv_t);
    cudaGetSymbolAddress((void**)&wdense_t, g_wdense_t);

    cudaFuncSetAttribute(gemm_mma_kernel,
                         cudaFuncAttributeMaxDynamicSharedMemorySize, SMEM_GEMM);
    cudaFuncSetAttribute(attn_mma_kernel,
                         cudaFuncAttributeMaxDynamicSharedMemorySize, ATT_SMEM);

    // 0) round inputs to tf32
    {
        int n4 = SQ * HID / 4;
        cvt_tf32_kernel<<<(n4 + 255) / 256, 256>>>(hidden, hid_t, n4);
        int w4 = QKV_N * HID / 4;
        cvt_tf32_kernel<<<(w4 + 255) / 256, 256>>>(w_qkv, wqkv_t, w4);
        int d4 = HID * HID / 4;
        cvt_tf32_kernel<<<(d4 + 255) / 256, 256>>>(w_dense, wdense_t, d4);
    }
    // 1) QKV projection: 256x128 tiles
    {
        dim3 grid(QKV_N / BN, SQ / BM);
        gemm_mma_kernel<<<grid, 512, SMEM_GEMM>>>(hid_t, wqkv_t, b_qkv, mixed,
                                                  QKV_N, HID);
    }
    // 2) rotary + tf32 rounding of q,k,v
    {
        int total = SQ * NHEAD * 64;
        rotary_kernel<<<(total + 255) / 256, 256>>>();
    }
    // 3) causal flash attention (tensor cores)
    {
        dim3 grid(SQ / 64, NHEAD);
        attn_mma_kernel<<<grid, 128, ATT_SMEM>>>();
    }
    // 4) dense: 256x128 tiles
    {
        dim3 grid(HID / BN, SQ / BM);
        gemm_mma_kernel<<<grid, 512, SMEM_GEMM>>>(ctx, wdense_t, nullptr, out,
                                                  HID, HID);
    }
}